// round 7
// baseline (speedup 1.0000x reference)
#include <cuda_runtime.h>
#include <cuda_bf16.h>
#include <cuda_fp16.h>
#include <cstdint>

#define NN 100000
#define NE 1600000
#define KP 136   // padded K stride (bf16): row stride 68 words -> ldmatrix conflict-free

// ---------------- device scratch ----------------
__device__ __half g_y[NN * 128];     // neighbor projection, fp16 (gather traffic /2)
__device__ float g_s[NN * 128];      // self projection + bias, fp32
__device__ __nv_bfloat16 g_xh[NN * 128];
__device__ __nv_bfloat16 g_xl[NN * 128];
__device__ __nv_bfloat16 g_w1h[256 * 128], g_w1l[256 * 128];
__device__ __nv_bfloat16 g_w2h[256 * 128], g_w2l[256 * 128];
__device__ __nv_bfloat16 g_w3h[128 * 128], g_w3l[128 * 128];
__device__ float g_invdeg[NN];
__device__ int   g_rowptr[NN + 1];
__device__ int   g_cnt[NN];
__device__ int   g_tscan[NN];
__device__ int   g_bsum[128];
__device__ int   g_esrc[NE];

__device__ __forceinline__ uint32_t smem_u32(const void* p) {
    uint32_t a;
    asm("{ .reg .u64 t; cvta.to.shared.u64 t, %1; cvt.u32.u64 %0, t; }" : "=r"(a) : "l"(p));
    return a;
}

// ---------------- CSR build ----------------
__global__ void k_count(const int* __restrict__ dst) {
    int e = blockIdx.x * blockDim.x + threadIdx.x;
    if (e < NE) atomicAdd(&g_cnt[dst[e]], 1);
}
__global__ void k_scan1() {
    __shared__ int wsum[32];
    int i = blockIdx.x * 1024 + threadIdx.x;
    int lane = threadIdx.x & 31, wid = threadIdx.x >> 5;
    int v = (i < NN) ? g_cnt[i] : 0;
    int x = v;
#pragma unroll
    for (int o = 1; o < 32; o <<= 1) {
        int t = __shfl_up_sync(0xffffffffu, x, o);
        if (lane >= o) x += t;
    }
    if (lane == 31) wsum[wid] = x;
    __syncthreads();
    if (wid == 0) {
        int w = wsum[lane];
#pragma unroll
        for (int o = 1; o < 32; o <<= 1) {
            int t = __shfl_up_sync(0xffffffffu, w, o);
            if (lane >= o) w += t;
        }
        wsum[lane] = w;
    }
    __syncthreads();
    int off = wid ? wsum[wid - 1] : 0;
    int inc = x + off;
    if (i < NN) g_tscan[i] = inc;
    if (threadIdx.x == 1023) g_bsum[blockIdx.x] = inc;
}
// shfl-based exclusive scan of <=128 block sums (1 block, 128 thr)
__global__ void k_scan2(int nb) {
    __shared__ int wtot[4];
    int t = threadIdx.x;
    int lane = t & 31, wid = t >> 5;
    int v = (t < nb) ? g_bsum[t] : 0;
    int x = v;
#pragma unroll
    for (int o = 1; o < 32; o <<= 1) {
        int u = __shfl_up_sync(0xffffffffu, x, o);
        if (lane >= o) x += u;
    }
    if (lane == 31) wtot[wid] = x;
    __syncthreads();
    int pre = 0;
#pragma unroll
    for (int w = 0; w < 4; w++) pre += (w < wid) ? wtot[w] : 0;
    if (t < nb) g_bsum[t] = x - v + pre;
}
__global__ void k_scan3() {
    int i = blockIdx.x * blockDim.x + threadIdx.x;
    if (i < NN) {
        g_rowptr[i + 1] = g_tscan[i] + g_bsum[i >> 10];
        if (i == 0) g_rowptr[0] = 0;
        int d = g_cnt[i];
        g_invdeg[i] = 1.0f / (float)(d > 0 ? d : 1);
        g_cnt[i] = 0;
    }
}
__global__ void k_fill(const int* __restrict__ src, const int* __restrict__ dst) {
    int e = blockIdx.x * blockDim.x + threadIdx.x;
    if (e < NE) {
        int d = dst[e];
        int p = g_rowptr[d] + atomicAdd(&g_cnt[d], 1);
        g_esrc[p] = src[e];
    }
}

// ---------------- prep: all 3 weight pairs -> [n][k] K-major bf16 hi/lo; zero g_cnt ----------------
__global__ void k_prepAll(const float* __restrict__ Wn1, const float* __restrict__ Ws1,
                          const float* __restrict__ Wn2, const float* __restrict__ Ws2,
                          const float* __restrict__ Wn3, const float* __restrict__ Ws3,
                          __nv_bfloat16* __restrict__ w1h, __nv_bfloat16* __restrict__ w1l,
                          __nv_bfloat16* __restrict__ w2h, __nv_bfloat16* __restrict__ w2l,
                          __nv_bfloat16* __restrict__ w3h, __nv_bfloat16* __restrict__ w3l) {
    int gi = blockIdx.x * blockDim.x + threadIdx.x;
    if (gi < NN) g_cnt[gi] = 0;
    // segment 0: w1 (256*128), segment 1: w2 (256*128), segment 2: w3 (128*128)
    const float* Wn;
    const float* Ws;
    __nv_bfloat16 *oh, *ol;
    int idx, C;
    if (gi < 32768) {
        idx = gi; Wn = Wn1; Ws = Ws1; oh = w1h; ol = w1l; C = 128;
    } else if (gi < 65536) {
        idx = gi - 32768; Wn = Wn2; Ws = Ws2; oh = w2h; ol = w2l; C = 128;
    } else if (gi < 81920) {
        idx = gi - 65536; Wn = Wn3; Ws = Ws3; oh = w3h; ol = w3l; C = 40;
    } else {
        return;
    }
    int n = idx >> 7, k = idx & 127;
    float f = 0.f;
    if (n < C) f = Wn[k * C + n];
    else if (n < 2 * C) f = Ws[k * C + (n - C)];
    __nv_bfloat16 h = __float2bfloat16(f);
    oh[idx] = h;
    ol[idx] = __float2bfloat16(f - __bfloat162float(h));
}

// features -> bf16 hi/lo
__global__ void k_splitX(const float4* __restrict__ x4, uint2* __restrict__ xh2,
                         uint2* __restrict__ xl2) {
    int idx = blockIdx.x * blockDim.x + threadIdx.x;
    if (idx >= NN * 32) return;
    float4 v = x4[idx];
    __nv_bfloat16 hx = __float2bfloat16(v.x), hy = __float2bfloat16(v.y);
    __nv_bfloat16 hz = __float2bfloat16(v.z), hw = __float2bfloat16(v.w);
    __nv_bfloat162 h01(hx, hy), h23(hz, hw);
    __nv_bfloat162 l01(__float2bfloat16(v.x - __bfloat162float(hx)),
                       __float2bfloat16(v.y - __bfloat162float(hy)));
    __nv_bfloat162 l23(__float2bfloat16(v.z - __bfloat162float(hz)),
                       __float2bfloat16(v.w - __bfloat162float(hw)));
    xh2[idx] = make_uint2(*(uint32_t*)&h01, *(uint32_t*)&h23);
    xl2[idx] = make_uint2(*(uint32_t*)&l01, *(uint32_t*)&l23);
}

// ---------------- mma.sync bf16 dual GEMM, occ-2, ldmatrix fragments ----------------
__device__ __forceinline__ void mma_bf16(float (&c)[4], const uint32_t (&a)[4],
                                         const uint32_t b0, const uint32_t b1) {
    asm volatile(
        "mma.sync.aligned.m16n8k16.row.col.f32.bf16.bf16.f32 "
        "{%0,%1,%2,%3}, {%4,%5,%6,%7}, {%8,%9}, {%0,%1,%2,%3};\n"
        : "+f"(c[0]), "+f"(c[1]), "+f"(c[2]), "+f"(c[3])
        : "r"(a[0]), "r"(a[1]), "r"(a[2]), "r"(a[3]), "r"(b0), "r"(b1));
}
__device__ __forceinline__ void ldsm_x4(uint32_t (&r)[4], uint32_t addr) {
    asm volatile("ldmatrix.sync.aligned.m8n8.x4.shared.b16 {%0,%1,%2,%3}, [%4];"
                 : "=r"(r[0]), "=r"(r[1]), "=r"(r[2]), "=r"(r[3]) : "r"(addr));
}

__global__ __launch_bounds__(256, 2) void k_gemm_mma(
    const __nv_bfloat16* __restrict__ xh, const __nv_bfloat16* __restrict__ xl,
    const __nv_bfloat16* __restrict__ wh, const __nv_bfloat16* __restrict__ wl,
    const float* __restrict__ bias, int C,
    __half* __restrict__ y, float* __restrict__ s) {
    extern __shared__ __nv_bfloat16 smarr[];
    __nv_bfloat16* Ah = smarr;
    __nv_bfloat16* Al = Ah + 128 * KP;
    __nv_bfloat16* Bh = Al + 128 * KP;
    __nv_bfloat16* Bl = Bh + 64 * KP;

    int tid = threadIdx.x;
    int row0 = blockIdx.x * 128;
    int col0 = blockIdx.y * 64;

    for (int idx = tid; idx < 128 * 16; idx += 256) {
        int r = idx >> 4, k = (idx & 15) << 3;
        int grow = row0 + r;
        uint4 vh = make_uint4(0, 0, 0, 0), vl = vh;
        if (grow < NN) {
            vh = *(const uint4*)(xh + grow * 128 + k);
            vl = *(const uint4*)(xl + grow * 128 + k);
        }
        *(uint4*)(Ah + r * KP + k) = vh;
        *(uint4*)(Al + r * KP + k) = vl;
    }
    for (int idx = tid; idx < 64 * 16; idx += 256) {
        int n = idx >> 4, k = (idx & 15) << 3;
        *(uint4*)(Bh + n * KP + k) = *(const uint4*)(wh + (col0 + n) * 128 + k);
        *(uint4*)(Bl + n * KP + k) = *(const uint4*)(wl + (col0 + n) * 128 + k);
    }
    __syncthreads();

    int wid = tid >> 5, lane = tid & 31;
    int mbase = (wid >> 1) * 32;
    int nbase = (wid & 1) * 32;
    int r4 = lane >> 2, tg = lane & 3;

    uint32_t aBase = smem_u32(Ah);
    uint32_t alBase = smem_u32(Al);
    uint32_t bBase = smem_u32(Bh);
    uint32_t blBase = smem_u32(Bl);

    int aRow = mbase + (lane & 15);
    int aOff = aRow * KP + ((lane >> 4) << 3);
    int q = lane >> 3;
    int bRow = nbase + ((q >> 1) << 3) + (lane & 7);
    int bOff = bRow * KP + ((q & 1) << 3);

    float acc[2][4][4];
#pragma unroll
    for (int mi = 0; mi < 2; mi++)
#pragma unroll
        for (int ni = 0; ni < 4; ni++)
#pragma unroll
            for (int c = 0; c < 4; c++) acc[mi][ni][c] = 0.f;

#pragma unroll
    for (int kc = 0; kc < 8; kc++) {
        int k0 = kc * 16;
        uint32_t ah[2][4], al[2][4];
        ldsm_x4(ah[0], aBase + (aOff + k0) * 2);
        ldsm_x4(ah[1], aBase + (aOff + 16 * KP + k0) * 2);
        ldsm_x4(al[0], alBase + (aOff + k0) * 2);
        ldsm_x4(al[1], alBase + (aOff + 16 * KP + k0) * 2);
        uint32_t bh01[4], bh23[4], bl01[4], bl23[4];
        ldsm_x4(bh01, bBase + (bOff + k0) * 2);
        ldsm_x4(bh23, bBase + (bOff + 16 * KP + k0) * 2);
        ldsm_x4(bl01, blBase + (bOff + k0) * 2);
        ldsm_x4(bl23, blBase + (bOff + 16 * KP + k0) * 2);
#pragma unroll
        for (int mi = 0; mi < 2; mi++) {
            mma_bf16(acc[mi][0], ah[mi], bh01[0], bh01[1]);
            mma_bf16(acc[mi][1], ah[mi], bh01[2], bh01[3]);
            mma_bf16(acc[mi][2], ah[mi], bh23[0], bh23[1]);
            mma_bf16(acc[mi][3], ah[mi], bh23[2], bh23[3]);
            mma_bf16(acc[mi][0], al[mi], bh01[0], bh01[1]);
            mma_bf16(acc[mi][1], al[mi], bh01[2], bh01[3]);
            mma_bf16(acc[mi][2], al[mi], bh23[0], bh23[1]);
            mma_bf16(acc[mi][3], al[mi], bh23[2], bh23[3]);
            mma_bf16(acc[mi][0], ah[mi], bl01[0], bl01[1]);
            mma_bf16(acc[mi][1], ah[mi], bl01[2], bl01[3]);
            mma_bf16(acc[mi][2], ah[mi], bl23[0], bl23[1]);
            mma_bf16(acc[mi][3], ah[mi], bl23[2], bl23[3]);
        }
    }

#pragma unroll
    for (int mi = 0; mi < 2; mi++) {
#pragma unroll
        for (int ni = 0; ni < 4; ni++) {
            int grow0 = row0 + mbase + mi * 16 + r4;
            int cc = col0 + nbase + ni * 8 + tg * 2;
            if (cc >= 2 * C) continue;
#pragma unroll
            for (int half = 0; half < 2; half++) {
                int grow = grow0 + half * 8;
                if (grow >= NN) continue;
                float v0 = acc[mi][ni][half * 2 + 0];
                float v1 = acc[mi][ni][half * 2 + 1];
                if (cc < C) {
                    __half2 hv = __floats2half2_rn(v0, v1);
                    *(uint32_t*)(y + grow * C + cc) = *(uint32_t*)&hv;
                } else {
                    int c = cc - C;
                    *(float2*)(s + grow * C + c) =
                        make_float2(v0 + bias[c], v1 + bias[c + 1]);
                }
            }
        }
    }
}

// ---------------- gather (fp16 y), software-pipelined MLP=16, F=128 ----------------
__global__ void k_aggfin128sp(const uint2* __restrict__ y2, const float4* __restrict__ s4,
                              uint2* __restrict__ xh2, uint2* __restrict__ xl2) {
    int n = (blockIdx.x * blockDim.x + threadIdx.x) >> 5;
    int lane = threadIdx.x & 31;
    if (n >= NN) return;
    int r0 = g_rowptr[n], r1 = g_rowptr[n + 1];
    float4 acc = make_float4(0.f, 0.f, 0.f, 0.f);
    for (int base = r0; base < r1; base += 32) {
        int idx = base + lane;
        int sid = (idx < r1) ? g_esrc[idx] : 0;
        int m = r1 - base;
        if (m > 32) m = 32;
        for (int j0 = 0; j0 < m; j0 += 16) {
            int cnt = m - j0;
            uint2 v[16];
#pragma unroll
            for (int t = 0; t < 16; t++) {
                int sn = __shfl_sync(0xffffffffu, sid, j0 + t);
                if (t < cnt) v[t] = y2[sn * 32 + lane];
            }
#pragma unroll
            for (int t = 0; t < 16; t++) {
                if (t < cnt) {
                    float2 p0 = __half22float2(*(__half2*)&v[t].x);
                    float2 p1 = __half22float2(*(__half2*)&v[t].y);
                    acc.x += p0.x; acc.y += p0.y; acc.z += p1.x; acc.w += p1.y;
                }
            }
        }
    }
    float id = g_invdeg[n];
    float4 sv = s4[n * 32 + lane];
    float4 o;
    o.x = fmaxf(sv.x + acc.x * id, 0.f);
    o.y = fmaxf(sv.y + acc.y * id, 0.f);
    o.z = fmaxf(sv.z + acc.z * id, 0.f);
    o.w = fmaxf(sv.w + acc.w * id, 0.f);
    __nv_bfloat16 hx = __float2bfloat16(o.x), hy = __float2bfloat16(o.y);
    __nv_bfloat16 hz = __float2bfloat16(o.z), hw = __float2bfloat16(o.w);
    __nv_bfloat162 h01(hx, hy), h23(hz, hw);
    __nv_bfloat162 l01(__float2bfloat16(o.x - __bfloat162float(hx)),
                       __float2bfloat16(o.y - __bfloat162float(hy)));
    __nv_bfloat162 l23(__float2bfloat16(o.z - __bfloat162float(hz)),
                       __float2bfloat16(o.w - __bfloat162float(hw)));
    xh2[n * 32 + lane] = make_uint2(*(uint32_t*)&h01, *(uint32_t*)&h23);
    xl2[n * 32 + lane] = make_uint2(*(uint32_t*)&l01, *(uint32_t*)&l23);
}

// ---------------- gather (fp16 y), pipelined, F=40 ----------------
__global__ void k_aggfin40(const uint32_t* __restrict__ y32, const float* __restrict__ s,
                           float* __restrict__ out) {
    int n = (blockIdx.x * blockDim.x + threadIdx.x) >> 5;
    int lane = threadIdx.x & 31;
    if (n >= NN) return;
    int r0 = g_rowptr[n], r1 = g_rowptr[n + 1];
    float2 acc = make_float2(0.f, 0.f);
    bool act = lane < 20;
    for (int base = r0; base < r1; base += 32) {
        int idx = base + lane;
        int sid = (idx < r1) ? g_esrc[idx] : 0;
        int m = r1 - base;
        if (m > 32) m = 32;
        for (int j0 = 0; j0 < m; j0 += 16) {
            int cnt = m - j0;
            uint32_t v[16];
#pragma unroll
            for (int t = 0; t < 16; t++) {
                int sn = __shfl_sync(0xffffffffu, sid, j0 + t);
                if (t < cnt && act) v[t] = y32[sn * 20 + lane];
            }
#pragma unroll
            for (int t = 0; t < 16; t++) {
                if (t < cnt && act) {
                    float2 p = __half22float2(*(__half2*)&v[t]);
                    acc.x += p.x; acc.y += p.y;
                }
            }
        }
    }
    if (act) {
        float id = g_invdeg[n];
        const float* sr = s + n * 40 + lane * 2;
        float2 o = make_float2(sr[0] + acc.x * id, sr[1] + acc.y * id);
        *(float2*)(out + n * 40 + lane * 2) = o;
    }
}

// ---------------- launch ----------------
extern "C" void kernel_launch(void* const* d_in, const int* in_sizes, int n_in,
                              void* d_out, int out_size) {
    const float* feat = (const float*)d_in[0];
    const int* src = (const int*)d_in[1];
    const int* dst = (const int*)d_in[2];
    const float* Ws1 = (const float*)d_in[3];
    const float* Wn1 = (const float*)d_in[4];
    const float* b1  = (const float*)d_in[5];
    const float* Ws2 = (const float*)d_in[6];
    const float* Wn2 = (const float*)d_in[7];
    const float* b2  = (const float*)d_in[8];
    const float* Ws3 = (const float*)d_in[9];
    const float* Wn3 = (const float*)d_in[10];
    const float* b3  = (const float*)d_in[11];
    float* out = (float*)d_out;

    __half* py;
    float* ps;
    __nv_bfloat16 *pxh, *pxl, *pw1h, *pw1l, *pw2h, *pw2l, *pw3h, *pw3l;
    cudaGetSymbolAddress((void**)&py, g_y);
    cudaGetSymbolAddress((void**)&ps, g_s);
    cudaGetSymbolAddress((void**)&pxh, g_xh);
    cudaGetSymbolAddress((void**)&pxl, g_xl);
    cudaGetSymbolAddress((void**)&pw1h, g_w1h);
    cudaGetSymbolAddress((void**)&pw1l, g_w1l);
    cudaGetSymbolAddress((void**)&pw2h, g_w2h);
    cudaGetSymbolAddress((void**)&pw2l, g_w2l);
    cudaGetSymbolAddress((void**)&pw3h, g_w3h);
    cudaGetSymbolAddress((void**)&pw3l, g_w3l);

    const int SMEM = (128 + 128 + 64 + 64) * KP * 2;  // 104448
    cudaFuncSetAttribute(k_gemm_mma, cudaFuncAttributeMaxDynamicSharedMemorySize, SMEM);

    int nbE = (NE + 255) / 256;
    int nbN = (NN + 255) / 256;
    int nbScan = (NN + 1023) / 1024;
    int gRows = (NN + 127) / 128;   // 782
    int gAgg = (NN + 7) / 8;

    // prep: all weights + zero g_cnt (one kernel), features split
    k_prepAll<<<(NN + 255) / 256, 256>>>(Wn1, Ws1, Wn2, Ws2, Wn3, Ws3,
                                         pw1h, pw1l, pw2h, pw2l, pw3h, pw3l);
    k_splitX<<<(NN * 32 + 255) / 256, 256>>>((const float4*)feat, (uint2*)pxh, (uint2*)pxl);

    // CSR build
    k_count<<<nbE, 256>>>(dst);
    k_scan1<<<nbScan, 1024>>>();
    k_scan2<<<1, 128>>>(nbScan);
    k_scan3<<<nbN, 256>>>();
    k_fill<<<nbE, 256>>>(src, dst);

    // layer 1
    k_gemm_mma<<<dim3(gRows, 4), 256, SMEM>>>(pxh, pxl, pw1h, pw1l, b1, 128, py, ps);
    k_aggfin128sp<<<gAgg, 256>>>((const uint2*)py, (const float4*)ps, (uint2*)pxh, (uint2*)pxl);
    // layer 2
    k_gemm_mma<<<dim3(gRows, 4), 256, SMEM>>>(pxh, pxl, pw2h, pw2l, b2, 128, py, ps);
    k_aggfin128sp<<<gAgg, 256>>>((const uint2*)py, (const float4*)ps, (uint2*)pxh, (uint2*)pxl);
    // layer 3 (N padded to 128: cols 0..39 -> y fp16, 40..79 -> s)
    k_gemm_mma<<<dim3(gRows, 2), 256, SMEM>>>(pxh, pxl, pw3h, pw3l, b3, 40, py, ps);
    k_aggfin40<<<gAgg, 256>>>((const uint32_t*)py, ps, out);
}

// round 8
// speedup vs baseline: 1.1981x; 1.1981x over previous
#include <cuda_runtime.h>
#include <cuda_bf16.h>
#include <cuda_fp16.h>
#include <cstdint>

#define NN 100000
#define NE 1600000
#define KP 136   // padded K stride (bf16): row stride 68 words -> ldmatrix conflict-free

// ---------------- device scratch ----------------
__device__ __half g_y[NN * 128];     // neighbor projection, fp16
__device__ float g_s[NN * 128];      // self projection + bias, fp32
__device__ __nv_bfloat16 g_xh[NN * 128];
__device__ __nv_bfloat16 g_xl[NN * 128];
__device__ __nv_bfloat16 g_w1h[256 * 128], g_w1l[256 * 128];
__device__ __nv_bfloat16 g_w2h[256 * 128], g_w2l[256 * 128];
__device__ __nv_bfloat16 g_w3h[128 * 128], g_w3l[128 * 128];
__device__ float g_invdeg[NN];
__device__ int   g_rowptr[NN + 1];
__device__ int   g_cnt[NN];          // zero at entry of every run (drained by k_fill)
__device__ int   g_tscan[NN];
__device__ int   g_bsum[128];
__device__ int   g_esrc[NE];

__device__ __forceinline__ uint32_t smem_u32(const void* p) {
    uint32_t a;
    asm("{ .reg .u64 t; cvta.to.shared.u64 t, %1; cvt.u32.u64 %0, t; }" : "=r"(a) : "l"(p));
    return a;
}

// ---------------- fused front: weight split + feature split + degree count ----------------
// Invariant: g_cnt == 0 at kernel entry (static init on first run; k_fill drains it
// back to zero every run), so counting needs no zeroing pass.
__global__ void k_front(const float4* __restrict__ x4, uint2* __restrict__ xh2,
                        uint2* __restrict__ xl2, const int* __restrict__ dst,
                        const float* __restrict__ Wn1, const float* __restrict__ Ws1,
                        const float* __restrict__ Wn2, const float* __restrict__ Ws2,
                        const float* __restrict__ Wn3, const float* __restrict__ Ws3,
                        __nv_bfloat16* __restrict__ w1h, __nv_bfloat16* __restrict__ w1l,
                        __nv_bfloat16* __restrict__ w2h, __nv_bfloat16* __restrict__ w2l,
                        __nv_bfloat16* __restrict__ w3h, __nv_bfloat16* __restrict__ w3l) {
    int idx = blockIdx.x * blockDim.x + threadIdx.x;
    // feature split (3.2M threads)
    if (idx < NN * 32) {
        float4 v = x4[idx];
        __nv_bfloat16 hx = __float2bfloat16(v.x), hy = __float2bfloat16(v.y);
        __nv_bfloat16 hz = __float2bfloat16(v.z), hw = __float2bfloat16(v.w);
        __nv_bfloat162 h01(hx, hy), h23(hz, hw);
        __nv_bfloat162 l01(__float2bfloat16(v.x - __bfloat162float(hx)),
                           __float2bfloat16(v.y - __bfloat162float(hy)));
        __nv_bfloat162 l23(__float2bfloat16(v.z - __bfloat162float(hz)),
                           __float2bfloat16(v.w - __bfloat162float(hw)));
        xh2[idx] = make_uint2(*(uint32_t*)&h01, *(uint32_t*)&h23);
        xl2[idx] = make_uint2(*(uint32_t*)&l01, *(uint32_t*)&l23);
    }
    // degree count (1.6M threads)
    if (idx < NE) atomicAdd(&g_cnt[dst[idx]], 1);
    // weight split (81920 threads)
    if (idx < 81920) {
        const float* Wn;
        const float* Ws;
        __nv_bfloat16 *oh, *ol;
        int wi, C;
        if (idx < 32768) {
            wi = idx; Wn = Wn1; Ws = Ws1; oh = w1h; ol = w1l; C = 128;
        } else if (idx < 65536) {
            wi = idx - 32768; Wn = Wn2; Ws = Ws2; oh = w2h; ol = w2l; C = 128;
        } else {
            wi = idx - 65536; Wn = Wn3; Ws = Ws3; oh = w3h; ol = w3l; C = 40;
        }
        int n = wi >> 7, k = wi & 127;
        float f = 0.f;
        if (n < C) f = Wn[k * C + n];
        else if (n < 2 * C) f = Ws[k * C + (n - C)];
        __nv_bfloat16 h = __float2bfloat16(f);
        oh[wi] = h;
        ol[wi] = __float2bfloat16(f - __bfloat162float(h));
    }
}

// ---------------- CSR scan ----------------
__global__ void k_scan1() {
    __shared__ int wsum[32];
    int i = blockIdx.x * 1024 + threadIdx.x;
    int lane = threadIdx.x & 31, wid = threadIdx.x >> 5;
    int v = (i < NN) ? g_cnt[i] : 0;
    int x = v;
#pragma unroll
    for (int o = 1; o < 32; o <<= 1) {
        int t = __shfl_up_sync(0xffffffffu, x, o);
        if (lane >= o) x += t;
    }
    if (lane == 31) wsum[wid] = x;
    __syncthreads();
    if (wid == 0) {
        int w = wsum[lane];
#pragma unroll
        for (int o = 1; o < 32; o <<= 1) {
            int t = __shfl_up_sync(0xffffffffu, w, o);
            if (lane >= o) w += t;
        }
        wsum[lane] = w;
    }
    __syncthreads();
    int off = wid ? wsum[wid - 1] : 0;
    int inc = x + off;
    if (i < NN) g_tscan[i] = inc;
    if (threadIdx.x == 1023) g_bsum[blockIdx.x] = inc;
}
__global__ void k_scan2(int nb) {
    __shared__ int wtot[4];
    int t = threadIdx.x;
    int lane = t & 31, wid = t >> 5;
    int v = (t < nb) ? g_bsum[t] : 0;
    int x = v;
#pragma unroll
    for (int o = 1; o < 32; o <<= 1) {
        int u = __shfl_up_sync(0xffffffffu, x, o);
        if (lane >= o) x += u;
    }
    if (lane == 31) wtot[wid] = x;
    __syncthreads();
    int pre = 0;
#pragma unroll
    for (int w = 0; w < 4; w++) pre += (w < wid) ? wtot[w] : 0;
    if (t < nb) g_bsum[t] = x - v + pre;
}
__global__ void k_scan3() {
    int i = blockIdx.x * blockDim.x + threadIdx.x;
    if (i < NN) {
        g_rowptr[i + 1] = g_tscan[i] + g_bsum[i >> 10];
        if (i == 0) g_rowptr[0] = 0;
        int d = g_cnt[i];
        g_invdeg[i] = 1.0f / (float)(d > 0 ? d : 1);
        // NOTE: no reset — k_fill drains g_cnt back to 0
    }
}
// claims slots by draining the counter: after this kernel g_cnt is all zeros again
__global__ void k_fill(const int* __restrict__ src, const int* __restrict__ dst) {
    int e = blockIdx.x * blockDim.x + threadIdx.x;
    if (e < NE) {
        int d = dst[e];
        int p = g_rowptr[d] + atomicSub(&g_cnt[d], 1) - 1;
        g_esrc[p] = src[e];
    }
}

// ---------------- mma.sync bf16 dual GEMM, occ-2, ldmatrix fragments ----------------
__device__ __forceinline__ void mma_bf16(float (&c)[4], const uint32_t (&a)[4],
                                         const uint32_t b0, const uint32_t b1) {
    asm volatile(
        "mma.sync.aligned.m16n8k16.row.col.f32.bf16.bf16.f32 "
        "{%0,%1,%2,%3}, {%4,%5,%6,%7}, {%8,%9}, {%0,%1,%2,%3};\n"
        : "+f"(c[0]), "+f"(c[1]), "+f"(c[2]), "+f"(c[3])
        : "r"(a[0]), "r"(a[1]), "r"(a[2]), "r"(a[3]), "r"(b0), "r"(b1));
}
__device__ __forceinline__ void ldsm_x4(uint32_t (&r)[4], uint32_t addr) {
    asm volatile("ldmatrix.sync.aligned.m8n8.x4.shared.b16 {%0,%1,%2,%3}, [%4];"
                 : "=r"(r[0]), "=r"(r[1]), "=r"(r[2]), "=r"(r[3]) : "r"(addr));
}

__global__ __launch_bounds__(256, 2) void k_gemm_mma(
    const __nv_bfloat16* __restrict__ xh, const __nv_bfloat16* __restrict__ xl,
    const __nv_bfloat16* __restrict__ wh, const __nv_bfloat16* __restrict__ wl,
    const float* __restrict__ bias, int C,
    __half* __restrict__ y, float* __restrict__ s) {
    extern __shared__ __nv_bfloat16 smarr[];
    __nv_bfloat16* Ah = smarr;
    __nv_bfloat16* Al = Ah + 128 * KP;
    __nv_bfloat16* Bh = Al + 128 * KP;
    __nv_bfloat16* Bl = Bh + 64 * KP;

    int tid = threadIdx.x;
    int row0 = blockIdx.x * 128;
    int col0 = blockIdx.y * 64;

    for (int idx = tid; idx < 128 * 16; idx += 256) {
        int r = idx >> 4, k = (idx & 15) << 3;
        int grow = row0 + r;
        uint4 vh = make_uint4(0, 0, 0, 0), vl = vh;
        if (grow < NN) {
            vh = *(const uint4*)(xh + grow * 128 + k);
            vl = *(const uint4*)(xl + grow * 128 + k);
        }
        *(uint4*)(Ah + r * KP + k) = vh;
        *(uint4*)(Al + r * KP + k) = vl;
    }
    for (int idx = tid; idx < 64 * 16; idx += 256) {
        int n = idx >> 4, k = (idx & 15) << 3;
        *(uint4*)(Bh + n * KP + k) = *(const uint4*)(wh + (col0 + n) * 128 + k);
        *(uint4*)(Bl + n * KP + k) = *(const uint4*)(wl + (col0 + n) * 128 + k);
    }
    __syncthreads();

    int wid = tid >> 5, lane = tid & 31;
    int mbase = (wid >> 1) * 32;
    int nbase = (wid & 1) * 32;
    int r4 = lane >> 2, tg = lane & 3;

    uint32_t aBase = smem_u32(Ah);
    uint32_t alBase = smem_u32(Al);
    uint32_t bBase = smem_u32(Bh);
    uint32_t blBase = smem_u32(Bl);

    int aRow = mbase + (lane & 15);
    int aOff = aRow * KP + ((lane >> 4) << 3);
    int q = lane >> 3;
    int bRow = nbase + ((q >> 1) << 3) + (lane & 7);
    int bOff = bRow * KP + ((q & 1) << 3);

    float acc[2][4][4];
#pragma unroll
    for (int mi = 0; mi < 2; mi++)
#pragma unroll
        for (int ni = 0; ni < 4; ni++)
#pragma unroll
            for (int c = 0; c < 4; c++) acc[mi][ni][c] = 0.f;

#pragma unroll
    for (int kc = 0; kc < 8; kc++) {
        int k0 = kc * 16;
        uint32_t ah[2][4], al[2][4];
        ldsm_x4(ah[0], aBase + (aOff + k0) * 2);
        ldsm_x4(ah[1], aBase + (aOff + 16 * KP + k0) * 2);
        ldsm_x4(al[0], alBase + (aOff + k0) * 2);
        ldsm_x4(al[1], alBase + (aOff + 16 * KP + k0) * 2);
        uint32_t bh01[4], bh23[4], bl01[4], bl23[4];
        ldsm_x4(bh01, bBase + (bOff + k0) * 2);
        ldsm_x4(bh23, bBase + (bOff + 16 * KP + k0) * 2);
        ldsm_x4(bl01, blBase + (bOff + k0) * 2);
        ldsm_x4(bl23, blBase + (bOff + 16 * KP + k0) * 2);
#pragma unroll
        for (int mi = 0; mi < 2; mi++) {
            mma_bf16(acc[mi][0], ah[mi], bh01[0], bh01[1]);
            mma_bf16(acc[mi][1], ah[mi], bh01[2], bh01[3]);
            mma_bf16(acc[mi][2], ah[mi], bh23[0], bh23[1]);
            mma_bf16(acc[mi][3], ah[mi], bh23[2], bh23[3]);
            mma_bf16(acc[mi][0], al[mi], bh01[0], bh01[1]);
            mma_bf16(acc[mi][1], al[mi], bh01[2], bh01[3]);
            mma_bf16(acc[mi][2], al[mi], bh23[0], bh23[1]);
            mma_bf16(acc[mi][3], al[mi], bh23[2], bh23[3]);
            mma_bf16(acc[mi][0], ah[mi], bl01[0], bl01[1]);
            mma_bf16(acc[mi][1], ah[mi], bl01[2], bl01[3]);
            mma_bf16(acc[mi][2], ah[mi], bl23[0], bl23[1]);
            mma_bf16(acc[mi][3], ah[mi], bl23[2], bl23[3]);
        }
    }

#pragma unroll
    for (int mi = 0; mi < 2; mi++) {
#pragma unroll
        for (int ni = 0; ni < 4; ni++) {
            int grow0 = row0 + mbase + mi * 16 + r4;
            int cc = col0 + nbase + ni * 8 + tg * 2;
            if (cc >= 2 * C) continue;
#pragma unroll
            for (int half = 0; half < 2; half++) {
                int grow = grow0 + half * 8;
                if (grow >= NN) continue;
                float v0 = acc[mi][ni][half * 2 + 0];
                float v1 = acc[mi][ni][half * 2 + 1];
                if (cc < C) {
                    __half2 hv = __floats2half2_rn(v0, v1);
                    *(uint32_t*)(y + grow * C + cc) = *(uint32_t*)&hv;
                } else {
                    int c = cc - C;
                    *(float2*)(s + grow * C + c) =
                        make_float2(v0 + bias[c], v1 + bias[c + 1]);
                }
            }
        }
    }
}

// ---------------- gather (fp16 y) + finalize (F=128) -> bf16 hi/lo [R6 proven form] ----------------
__global__ void k_aggfin128sp(const uint2* __restrict__ y2, const float4* __restrict__ s4,
                              uint2* __restrict__ xh2, uint2* __restrict__ xl2) {
    int n = (blockIdx.x * blockDim.x + threadIdx.x) >> 5;
    int lane = threadIdx.x & 31;
    if (n >= NN) return;
    int r0 = g_rowptr[n], r1 = g_rowptr[n + 1];
    float4 acc = make_float4(0.f, 0.f, 0.f, 0.f);
    for (int base = r0; base < r1; base += 32) {
        int idx = base + lane;
        int sid = (idx < r1) ? g_esrc[idx] : 0;
        int m = r1 - base;
        if (m > 32) m = 32;
#pragma unroll 4
        for (int j = 0; j < m; j++) {
            int sn = __shfl_sync(0xffffffffu, sid, j);
            uint2 v = y2[sn * 32 + lane];
            float2 p0 = __half22float2(*(__half2*)&v.x);
            float2 p1 = __half22float2(*(__half2*)&v.y);
            acc.x += p0.x; acc.y += p0.y; acc.z += p1.x; acc.w += p1.y;
        }
    }
    float id = g_invdeg[n];
    float4 sv = s4[n * 32 + lane];
    float4 o;
    o.x = fmaxf(sv.x + acc.x * id, 0.f);
    o.y = fmaxf(sv.y + acc.y * id, 0.f);
    o.z = fmaxf(sv.z + acc.z * id, 0.f);
    o.w = fmaxf(sv.w + acc.w * id, 0.f);
    __nv_bfloat16 hx = __float2bfloat16(o.x), hy = __float2bfloat16(o.y);
    __nv_bfloat16 hz = __float2bfloat16(o.z), hw = __float2bfloat16(o.w);
    __nv_bfloat162 h01(hx, hy), h23(hz, hw);
    __nv_bfloat162 l01(__float2bfloat16(o.x - __bfloat162float(hx)),
                       __float2bfloat16(o.y - __bfloat162float(hy)));
    __nv_bfloat162 l23(__float2bfloat16(o.z - __bfloat162float(hz)),
                       __float2bfloat16(o.w - __bfloat162float(hw)));
    xh2[n * 32 + lane] = make_uint2(*(uint32_t*)&h01, *(uint32_t*)&h23);
    xl2[n * 32 + lane] = make_uint2(*(uint32_t*)&l01, *(uint32_t*)&l23);
}

// ---------------- gather (fp16 y) + finalize (F=40) [R6 proven form] ----------------
__global__ void k_aggfin40(const uint32_t* __restrict__ y32, const float* __restrict__ s,
                           float* __restrict__ out) {
    int n = (blockIdx.x * blockDim.x + threadIdx.x) >> 5;
    int lane = threadIdx.x & 31;
    if (n >= NN) return;
    int r0 = g_rowptr[n], r1 = g_rowptr[n + 1];
    float2 acc = make_float2(0.f, 0.f);
    for (int base = r0; base < r1; base += 32) {
        int idx = base + lane;
        int sid = (idx < r1) ? g_esrc[idx] : 0;
        int m = r1 - base;
        if (m > 32) m = 32;
#pragma unroll 4
        for (int j = 0; j < m; j++) {
            int sn = __shfl_sync(0xffffffffu, sid, j);
            if (lane < 20) {
                uint32_t v = y32[sn * 20 + lane];
                float2 p = __half22float2(*(__half2*)&v);
                acc.x += p.x; acc.y += p.y;
            }
        }
    }
    if (lane < 20) {
        float id = g_invdeg[n];
        const float* sr = s + n * 40 + lane * 2;
        float2 o = make_float2(sr[0] + acc.x * id, sr[1] + acc.y * id);
        *(float2*)(out + n * 40 + lane * 2) = o;
    }
}

// ---------------- launch ----------------
extern "C" void kernel_launch(void* const* d_in, const int* in_sizes, int n_in,
                              void* d_out, int out_size) {
    const float* feat = (const float*)d_in[0];
    const int* src = (const int*)d_in[1];
    const int* dst = (const int*)d_in[2];
    const float* Ws1 = (const float*)d_in[3];
    const float* Wn1 = (const float*)d_in[4];
    const float* b1  = (const float*)d_in[5];
    const float* Ws2 = (const float*)d_in[6];
    const float* Wn2 = (const float*)d_in[7];
    const float* b2  = (const float*)d_in[8];
    const float* Ws3 = (const float*)d_in[9];
    const float* Wn3 = (const float*)d_in[10];
    const float* b3  = (const float*)d_in[11];
    float* out = (float*)d_out;

    __half* py;
    float* ps;
    __nv_bfloat16 *pxh, *pxl, *pw1h, *pw1l, *pw2h, *pw2l, *pw3h, *pw3l;
    cudaGetSymbolAddress((void**)&py, g_y);
    cudaGetSymbolAddress((void**)&ps, g_s);
    cudaGetSymbolAddress((void**)&pxh, g_xh);
    cudaGetSymbolAddress((void**)&pxl, g_xl);
    cudaGetSymbolAddress((void**)&pw1h, g_w1h);
    cudaGetSymbolAddress((void**)&pw1l, g_w1l);
    cudaGetSymbolAddress((void**)&pw2h, g_w2h);
    cudaGetSymbolAddress((void**)&pw2l, g_w2l);
    cudaGetSymbolAddress((void**)&pw3h, g_w3h);
    cudaGetSymbolAddress((void**)&pw3l, g_w3l);

    const int SMEM = (128 + 128 + 64 + 64) * KP * 2;  // 104448
    cudaFuncSetAttribute(k_gemm_mma, cudaFuncAttributeMaxDynamicSharedMemorySize, SMEM);

    int nbE = (NE + 255) / 256;
    int nbN = (NN + 255) / 256;
    int nbScan = (NN + 1023) / 1024;
    int gRows = (NN + 127) / 128;   // 782
    int gAgg = (NN + 7) / 8;

    // fused front: feature split + weight split + degree count (g_cnt==0 invariant)
    k_front<<<(NN * 32 + 255) / 256, 256>>>(
        (const float4*)feat, (uint2*)pxh, (uint2*)pxl, dst,
        Wn1, Ws1, Wn2, Ws2, Wn3, Ws3,
        pw1h, pw1l, pw2h, pw2l, pw3h, pw3l);

    // CSR scan + fill (fill drains g_cnt back to zero)
    k_scan1<<<nbScan, 1024>>>();
    k_scan2<<<1, 128>>>(nbScan);
    k_scan3<<<nbN, 256>>>();
    k_fill<<<nbE, 256>>>(src, dst);

    // layer 1
    k_gemm_mma<<<dim3(gRows, 4), 256, SMEM>>>(pxh, pxl, pw1h, pw1l, b1, 128, py, ps);
    k_aggfin128sp<<<gAgg, 256>>>((const uint2*)py, (const float4*)ps, (uint2*)pxh, (uint2*)pxl);
    // layer 2
    k_gemm_mma<<<dim3(gRows, 4), 256, SMEM>>>(pxh, pxl, pw2h, pw2l, b2, 128, py, ps);
    k_aggfin128sp<<<gAgg, 256>>>((const uint2*)py, (const float4*)ps, (uint2*)pxh, (uint2*)pxl);
    // layer 3
    k_gemm_mma<<<dim3(gRows, 2), 256, SMEM>>>(pxh, pxl, pw3h, pw3l, b3, 40, py, ps);
    k_aggfin40<<<gAgg, 256>>>((const uint32_t*)py, ps, out);
}